// round 17
// baseline (speedup 1.0000x reference)
#include <cuda_runtime.h>
#include <cuda_fp16.h>

// RoIAlign (torchvision aligned=True, sampling_ratio=2) — two-pass with
// asymmetric 5/3 stage split and HIGH-PRIORITY gather stream:
//   main:  T(b0..4) --e0--> T(b5..7) --e1
//   side*: wait e0 -> G(b0..4) ; wait e1 -> G(b5..7) --eJ--> join
// (*side stream created with greatest priority so G CTAs win dispatch slots
//  over T(b5..7) CTAs as they free -> true overlap.)
// Kernels identical to the R16 pair (proven: T ~29.5us w/ __ldcs, G ~20.4us).

#define B_    8
#define N_    64
#define C_    256
#define C2_   (C_ / 2)
#define H_    128
#define W_    128
#define HW_   (H_ * W_)
#define OUT_H 6
#define OUT_W 6
#define NPOS  36
#define PPB   18             // positions per gather block (half a box)
#define WPB   6              // warps per gather block
#define TPB   (WPB * 32)     // 192 threads
#define SPLIT 5              // batches in stage 1

// 8 * 16384 * 256 halves = 64 MB scratch (__device__ global: allowed)
__device__ __half g_xt[(size_t)B_ * HW_ * C_];

// ---------------------------------------------------------------------------
// Transpose batches [b0, b0+gridDim.z): [C, HW] f32 -> [HW, C] f16.
// __ldcs input reads (streaming) — measured ~13% faster than default.
// ---------------------------------------------------------------------------
__global__ void __launch_bounds__(256)
transpose_kernel(const float* __restrict__ x, int b0)
{
    __shared__ float sm[64][33];

    const int b  = b0 + blockIdx.z;
    const int c0 = blockIdx.y * 64;
    const int s0 = blockIdx.x * 32;
    const int tid = threadIdx.x;
    const int tx = tid & 31;
    const int ty = tid >> 5;

    const float* src = x + ((size_t)b * C_ + c0) * HW_ + s0;
    #pragma unroll
    for (int r = 0; r < 8; r++) {
        int cl = ty + 8 * r;
        sm[cl][tx] = __ldcs(src + (size_t)cl * HW_ + tx);
    }
    __syncthreads();

    const int sp = tid >> 3;
    const int g  = tid & 7;

    uint4 v;
    __half2* h2 = (__half2*)&v;
    #pragma unroll
    for (int k = 0; k < 4; k++) {
        float a = sm[8 * g + 2 * k + 0][sp];
        float c = sm[8 * g + 2 * k + 1][sp];
        h2[k] = __floats2half2_rn(a, c);
    }

    uint4* dst = (uint4*)g_xt;   // pixel stride = 32 uint4
    dst[((size_t)b * HW_ + s0 + sp) * 32 + (c0 >> 3) + g] = v;
}

// ---------------------------------------------------------------------------
// Gather batches [b0, ...). blockIdx.x = local bn*2 + half. Warp w handles
// local positions w, w+6, w+12; lane l covers channels 8l..8l+7 via one
// uint4 per corner (512B coalesced warp transactions).
// ---------------------------------------------------------------------------
__global__ void __launch_bounds__(TPB)
gather_kernel(const float* __restrict__ boxes, float* __restrict__ out, int b0)
{
    __shared__ float tile[PPB][C_ + 2];   // row stride 258 floats

    const int blk  = blockIdx.x;
    const int bn   = b0 * N_ + (blk >> 1);
    const int half = blk & 1;             // oh rows 0-2 or 3-5
    const int b    = bn >> 6;
    const int tid  = threadIdx.x;
    const int lane = tid & 31;
    const int w    = tid >> 5;

    const float* box = boxes + bn * 4;
    const float bx1 = __ldg(box + 0) - 0.5f;
    const float by1 = __ldg(box + 1) - 0.5f;
    const float bx2 = __ldg(box + 2) - 0.5f;
    const float by2 = __ldg(box + 3) - 0.5f;
    const float bw = (bx2 - bx1) * (1.0f / OUT_W);
    const float bh = (by2 - by1) * (1.0f / OUT_H);

    const uint4* xt4 = (const uint4*)g_xt + (size_t)b * HW_ * 32 + lane;

    #pragma unroll
    for (int pl = 0; pl < 3; pl++) {
        const int pos  = w + 6 * pl;               // 0..17 local
        const int gpos = half * PPB + pos;         // 0..35 global
        const int oh = gpos / 6;
        const int ow = gpos - 6 * oh;

        int   yl[2], yh[2], xl[2], xh[2];
        float wy0[2], wy1[2], wx0[2], wx1[2];
        #pragma unroll
        for (int i = 0; i < 2; i++) {
            float yy = by1 + ((float)oh + ((float)i + 0.5f) * 0.5f) * bh;
            bool  vy = (yy >= -1.0f) && (yy <= (float)H_);
            float cy = fmaxf(yy, 0.0f);
            int   lo = (int)floorf(cy);
            bool  ey = (lo >= H_ - 1);
            yl[i] = ey ? (H_ - 1) : lo;
            yh[i] = ey ? (H_ - 1) : (lo + 1);
            float fy = ey ? 0.0f : (cy - (float)lo);
            wy1[i] = vy ? fy : 0.0f;
            wy0[i] = vy ? (1.0f - fy) : 0.0f;

            float xx = bx1 + ((float)ow + ((float)i + 0.5f) * 0.5f) * bw;
            bool  vx = (xx >= -1.0f) && (xx <= (float)W_);
            float cx = fmaxf(xx, 0.0f);
            int   lx = (int)floorf(cx);
            bool  ex = (lx >= W_ - 1);
            xl[i] = ex ? (W_ - 1) : lx;
            xh[i] = ex ? (W_ - 1) : (lx + 1);
            float fx = ex ? 0.0f : (cx - (float)lx);
            // fold the 0.25 sample average (exact: power of two)
            wx1[i] = vx ? (fx * 0.25f) : 0.0f;
            wx0[i] = vx ? ((1.0f - fx) * 0.25f) : 0.0f;
        }

        float acc[8];
        #pragma unroll
        for (int k = 0; k < 8; k++) acc[k] = 0.0f;

        #pragma unroll
        for (int iy = 0; iy < 2; iy++) {
            #pragma unroll
            for (int ix = 0; ix < 2; ix++) {
                const int p00 = (yl[iy] * W_ + xl[ix]) * 32;
                const int p01 = (yl[iy] * W_ + xh[ix]) * 32;
                const int p10 = (yh[iy] * W_ + xl[ix]) * 32;
                const int p11 = (yh[iy] * W_ + xh[ix]) * 32;
                const float w00 = wy0[iy] * wx0[ix];
                const float w01 = wy0[iy] * wx1[ix];
                const float w10 = wy1[iy] * wx0[ix];
                const float w11 = wy1[iy] * wx1[ix];

                uint4 v00 = __ldg(xt4 + p00);
                uint4 v01 = __ldg(xt4 + p01);
                uint4 v10 = __ldg(xt4 + p10);
                uint4 v11 = __ldg(xt4 + p11);

                const uint4* vs[4] = { &v00, &v01, &v10, &v11 };
                const float  ws[4] = { w00, w01, w10, w11 };
                #pragma unroll
                for (int c4 = 0; c4 < 4; c4++) {
                    const __half2* h = (const __half2*)vs[c4];
                    const float wgt = ws[c4];
                    #pragma unroll
                    for (int j = 0; j < 4; j++) {
                        float2 f = __half22float2(h[j]);
                        acc[2 * j + 0] += wgt * f.x;
                        acc[2 * j + 1] += wgt * f.y;
                    }
                }
            }
        }

        float2* row = (float2*)&tile[pos][0];     // stride 258 -> 8B aligned
        #pragma unroll
        for (int j = 0; j < 4; j++) {
            row[4 * lane + j] = make_float2(acc[2 * j], acc[2 * j + 1]);
        }
    }
    __syncthreads();

    // Output slab: for each channel c, 18 contiguous floats at c*36 + half*18.
    float* obase = out + (size_t)bn * (C_ * NPOS) + half * PPB;
    int c = tid / PPB;
    int p = tid - PPB * c;
    #pragma unroll
    for (int i = 0; i < (C_ * PPB) / TPB; i++) {   // 24 iterations
        __stcs(obase + c * NPOS + p, tile[p][c]);
        c += 10; p += 12;
        if (p >= PPB) { p -= PPB; c += 1; }
    }
}

extern "C" void kernel_launch(void* const* d_in, const int* in_sizes, int n_in,
                              void* d_out, int out_size)
{
    const float* x     = (const float*)d_in[0];
    const float* boxes = (const float*)d_in[1];
    float*       out   = (float*)d_out;

    // High-priority side stream for the gathers (capture-safe; R9 pattern).
    int prio_lo, prio_hi;
    cudaDeviceGetStreamPriorityRange(&prio_lo, &prio_hi);  // hi = greatest
    cudaStream_t s2;
    cudaStreamCreateWithPriority(&s2, cudaStreamNonBlocking, prio_hi);
    cudaEvent_t e0, e1, eJ;
    cudaEventCreateWithFlags(&e0, cudaEventDisableTiming);
    cudaEventCreateWithFlags(&e1, cudaEventDisableTiming);
    cudaEventCreateWithFlags(&eJ, cudaEventDisableTiming);

    dim3 tg1(HW_ / 32, C_ / 64, SPLIT);          // 512 x 4 x 5
    dim3 tg2(HW_ / 32, C_ / 64, B_ - SPLIT);     // 512 x 4 x 3

    transpose_kernel<<<tg1, 256, 0, 0>>>(x, 0);
    cudaEventRecord(e0, 0);
    transpose_kernel<<<tg2, 256, 0, 0>>>(x, SPLIT);
    cudaEventRecord(e1, 0);

    cudaStreamWaitEvent(s2, e0, 0);
    gather_kernel<<<SPLIT * N_ * 2, TPB, 0, s2>>>(boxes, out, 0);
    cudaStreamWaitEvent(s2, e1, 0);
    gather_kernel<<<(B_ - SPLIT) * N_ * 2, TPB, 0, s2>>>(boxes, out, SPLIT);
    cudaEventRecord(eJ, s2);

    cudaStreamWaitEvent(0, eJ, 0);   // join back to the captured origin stream
}